// round 14
// baseline (speedup 1.0000x reference)
#include <cuda_runtime.h>

#define SLOPE 0.1f
#define LFRM  1024
#define CHANS 144
#define WINL  32
#define NWIN  993
#define MROWS (NWIN*CHANS)        // 142992
#define MTILES 1118
#define MPAD  (MTILES*128)        // 143104

typedef unsigned int u32;

// ---------------- device scratch (no cudaMalloc allowed) -------------------
__device__ float g_d6T[CHANS*LFRM];     // transposed: [ch][t]
__device__ float g_h[(size_t)MPAD*512];
__device__ float g_r[(size_t)MPAD*256];
__device__ float g_y[(size_t)MROWS*WINL];
// packed tf32 weight image: per layer, per K-chunk(32), per kp(16), per n:
// uint4 = (hi[k], hi[k+4], lo[k], lo[k+4]),  k = c*32 + (kp>>2)*8 + (kp&3)
#define WPK4 278528
__device__ __align__(16) uint4 g_wpk[WPK4];
#define Q1P 0
#define Q2P 8192
#define Q3P 73728
#define Q4P 139264
#define Q5P 204800
#define Q6P 270336

__device__ __forceinline__ float lrelu(float x){ return x >= 0.0f ? x : SLOPE*x; }

// ---------------- PTX helpers ----------------------------------------------
__device__ __forceinline__ u32 smem_u32(const void* p){
    u32 a; asm("{ .reg .u64 t; cvta.to.shared.u64 t, %1; cvt.u32.u64 %0, t; }" : "=r"(a) : "l"(p));
    return a;
}
__device__ __forceinline__ u32 tf32r(float x){
    u32 r; asm("cvt.rna.tf32.f32 %0, %1;" : "=r"(r) : "f"(x)); return r;
}
__device__ __forceinline__ void mma_tf32(float* d, const u32* a, u32 b0, u32 b1){
    asm volatile(
        "mma.sync.aligned.m16n8k8.row.col.f32.tf32.tf32.f32 "
        "{%0,%1,%2,%3}, {%4,%5,%6,%7}, {%8,%9}, {%0,%1,%2,%3};"
        : "+f"(d[0]), "+f"(d[1]), "+f"(d[2]), "+f"(d[3])
        : "r"(a[0]), "r"(a[1]), "r"(a[2]), "r"(a[3]), "r"(b0), "r"(b1));
}
#define CP16(dst, src) asm volatile("cp.async.cg.shared.global [%0], [%1], 16;" :: "r"(dst), "l"(src))
#define CP4(dst, src)  asm volatile("cp.async.ca.shared.global [%0], [%1], 4;"  :: "r"(dst), "l"(src))
#define CP_COMMIT()    asm volatile("cp.async.commit_group;" ::: "memory")
#define CP_WAIT(n)     asm volatile("cp.async.wait_group %0;" :: "n"(n) : "memory")

// truncation split: hi = v with low 13 mantissa bits zeroed (exact in fp32)
__device__ __forceinline__ u32 trunc_hi(float v){
    return __float_as_uint(v) & 0xFFFFE000u;
}

// ---------------------------------------------------------------------------
// Stage A: axis-angle -> 6D (transposed layout [ch][t])
// ---------------------------------------------------------------------------
__global__ void aa_to_d6_kernel(const float* __restrict__ dp){
    int idx = blockIdx.x*blockDim.x + threadIdx.x;
    if (idx >= LFRM*24) return;
    int t = idx/24, j = idx - 24*t;
    float x = dp[t*72+3*j], y = dp[t*72+3*j+1], z = dp[t*72+3*j+2];
    float ang = sqrtf(x*x + y*y + z*z);
    float inv = 1.0f / fmaxf(ang, 1e-8f);
    x *= inv; y *= inv; z *= inv;
    float s = sinf(ang), c = cosf(ang);
    float C = 1.0f - c;
    float* o = g_d6T + (size_t)(6*j)*LFRM + t;
    o[0*LFRM] = c + x*x*C;      o[1*LFRM] = x*y*C - z*s;   o[2*LFRM] = x*z*C + y*s;
    o[3*LFRM] = y*x*C + z*s;    o[4*LFRM] = c + y*y*C;     o[5*LFRM] = y*z*C - x*s;
}

// ---------------------------------------------------------------------------
// Weight prep: W[N][K] -> packed fragment image (one uint4 per thread)
// ---------------------------------------------------------------------------
__global__ void prep_kernel(const float* __restrict__ w_in, const float* __restrict__ w1a,
                            const float* __restrict__ w1b, const float* __restrict__ w2a,
                            const float* __restrict__ w2b, const float* __restrict__ w_out){
    int idx = blockIdx.x*blockDim.x + threadIdx.x;
    if (idx >= WPK4) return;
    int base, N, K; const float* W;
    if      (idx < Q2P){ base=Q1P; N=512; K=32;  W=w_in;  }
    else if (idx < Q3P){ base=Q2P; N=256; K=512; W=w1a;   }
    else if (idx < Q4P){ base=Q3P; N=512; K=256; W=w1b;   }
    else if (idx < Q5P){ base=Q4P; N=256; K=512; W=w2a;   }
    else if (idx < Q6P){ base=Q5P; N=512; K=256; W=w2b;   }
    else               { base=Q6P; N=32;  K=512; W=w_out; }
    int e = idx - base;
    int c  = e / (16*N);
    int rm = e - c*16*N;
    int kp = rm / N, n = rm - kp*N;
    int k  = c*32 + ((kp>>2)<<3) + (kp&3);
    float va = W[n*K + k], vb = W[n*K + k + 4];
    u32 ha = tf32r(va), hb = tf32r(vb);
    g_wpk[idx] = make_uint4(ha, hb,
                            tf32r(va - __uint_as_float(ha)),
                            tf32r(vb - __uint_as_float(hb)));
}

// ---------------------------------------------------------------------------
// GEMM: C[128 x NT per CTA] = act(A @ W^T + b) [+res], 3xTF32 on mma.sync.
// grid = (n-tiles, m-tiles): col-tile fast axis -> sibling CTAs share A in L2.
// 256 threads (MW x NW warp grid), 2 CTAs/SM. cp.async double-buffered K=32.
// A: fp32 smem, trunc-hi split, raw-bits lo. B: packed uint4, BSTR = NT.
// ---------------------------------------------------------------------------
template<int KTOT, int NT, int NFULL, int MW, int NW, bool GATHER, bool RELU, bool RES>
__global__ void __launch_bounds__(256, 2)
gemm_tc(const float* __restrict__ A, int ldA,
        const float* __restrict__ bias,
        float* __restrict__ C, int ldC,
        const float* __restrict__ res,
        const uint4* __restrict__ Wp)
{
    constexpr int KC = 32, NCH = KTOT/32;
    constexpr int WM = 128/MW, WN = NT/NW, MF = WM/16, NF = WN/8;
    constexpr int ASTR = 36, BSTR4 = NT;
    constexpr int AELE = 128*ASTR, BELE4 = 16*BSTR4;

    extern __shared__ float sm[];
    float* Ab[2] = { sm, sm + AELE };
    uint4* Bq[2];
    Bq[0] = (uint4*)(sm + 2*AELE);
    Bq[1] = Bq[0] + BELE4;

    const int tid = threadIdx.x, lane = tid & 31, wid = tid >> 5;
    const int gid = lane >> 2, tig = lane & 3;
    const int warp_n = wid % NW, warp_m = wid / NW;
    const int m0 = blockIdx.y * 128;
    const int col0 = blockIdx.x * NT;

    float acc[MF][NF][4];
    #pragma unroll
    for (int i = 0; i < MF; i++)
        #pragma unroll
        for (int j = 0; j < NF; j++)
            #pragma unroll
            for (int q = 0; q < 4; q++) acc[i][j][q] = 0.0f;

    auto stage = [&](int c, int b){
        if (GATHER){
            // transposed d6: k contiguous -> coalesced CP4
            for (int idx = tid; idx < 128*KC; idx += 256){
                int r = idx >> 5, k = idx & 31;
                int m = m0 + r; if (m >= MROWS) m = MROWS - 1;
                int n = m / CHANS, ch = m - n*CHANS;
                CP4(smem_u32(&Ab[b][r*ASTR + k]),
                    g_d6T + (size_t)ch*LFRM + n + c*KC + k);
            }
        } else {
            for (int idx = tid; idx < 128*8; idx += 256){
                int r = idx >> 3, q = idx & 7;
                CP16(smem_u32(&Ab[b][r*ASTR + 4*q]),
                     A + (size_t)(m0 + r)*ldA + c*KC + 4*q);
            }
        }
        for (int idx = tid; idx < 16*NT; idx += 256){
            int kp = idx / NT, n = idx % NT;
            CP16(smem_u32(&Bq[b][kp*BSTR4 + n]),
                 Wp + (size_t)(c*16 + kp)*NFULL + col0 + n);
        }
    };

    stage(0, 0); CP_COMMIT();
    if (NCH > 1){ stage(1, 1); CP_COMMIT(); }

    for (int c = 0; c < NCH; c++){
        if (c == NCH-1) { CP_WAIT(0); } else { CP_WAIT(1); }
        __syncthreads();
        int b = c & 1;
        const float* As = Ab[b];
        const uint4* Bs = Bq[b];
        #pragma unroll
        for (int ks = 0; ks < KC/8; ks++){
            int kk = ks*8 + tig;
            int kpr = ks*4 + tig;
            // ---- A fragments: trunc hi (LOP3), raw-bits lo (FADD only) ----
            u32 ah[MF][4], al[MF][4];
            #pragma unroll
            for (int mf = 0; mf < MF; mf++){
                int r0 = warp_m*WM + mf*16 + gid;
                float x0 = As[r0*ASTR + kk];
                float x1 = As[(r0+8)*ASTR + kk];
                float x2 = As[r0*ASTR + kk + 4];
                float x3 = As[(r0+8)*ASTR + kk + 4];
                ah[mf][0] = trunc_hi(x0); al[mf][0] = __float_as_uint(x0 - __uint_as_float(ah[mf][0]));
                ah[mf][1] = trunc_hi(x1); al[mf][1] = __float_as_uint(x1 - __uint_as_float(ah[mf][1]));
                ah[mf][2] = trunc_hi(x2); al[mf][2] = __float_as_uint(x2 - __uint_as_float(ah[mf][2]));
                ah[mf][3] = trunc_hi(x3); al[mf][3] = __float_as_uint(x3 - __uint_as_float(ah[mf][3]));
            }
            // ---- B fragments: one LDS.128 per nf ----
            uint4 bq[NF];
            #pragma unroll
            for (int nf = 0; nf < NF; nf++)
                bq[nf] = Bs[kpr*BSTR4 + warp_n*WN + nf*8 + gid];
            // ---- 3 term sweeps ----
            #pragma unroll
            for (int nf = 0; nf < NF; nf++)
                #pragma unroll
                for (int mf = 0; mf < MF; mf++)
                    mma_tf32(acc[mf][nf], ah[mf], bq[nf].x, bq[nf].y);
            #pragma unroll
            for (int nf = 0; nf < NF; nf++)
                #pragma unroll
                for (int mf = 0; mf < MF; mf++)
                    mma_tf32(acc[mf][nf], ah[mf], bq[nf].z, bq[nf].w);
            #pragma unroll
            for (int nf = 0; nf < NF; nf++)
                #pragma unroll
                for (int mf = 0; mf < MF; mf++)
                    mma_tf32(acc[mf][nf], al[mf], bq[nf].x, bq[nf].y);
        }
        if (c + 2 < NCH){
            __syncthreads();
            stage(c + 2, b); CP_COMMIT();
        }
    }

    // ---- epilogue ----
    #pragma unroll
    for (int mf = 0; mf < MF; mf++){
        int row = m0 + warp_m*WM + mf*16 + gid;
        #pragma unroll
        for (int nf = 0; nf < NF; nf++){
            int cn = col0 + warp_n*WN + nf*8 + 2*tig;
            float2 bv = *reinterpret_cast<const float2*>(bias + cn);
            float v0x = acc[mf][nf][0] + bv.x, v0y = acc[mf][nf][1] + bv.y;
            float v1x = acc[mf][nf][2] + bv.x, v1y = acc[mf][nf][3] + bv.y;
            if (RELU){ v0x = lrelu(v0x); v0y = lrelu(v0y); v1x = lrelu(v1x); v1y = lrelu(v1y); }
            if (row < MROWS){
                if (RES){
                    float2 rv = *reinterpret_cast<const float2*>(res + (size_t)row*ldC + cn);
                    v0x += rv.x; v0y += rv.y;
                }
                *reinterpret_cast<float2*>(C + (size_t)row*ldC + cn) = make_float2(v0x, v0y);
            }
            if (row + 8 < MROWS){
                if (RES){
                    float2 rv = *reinterpret_cast<const float2*>(res + (size_t)(row+8)*ldC + cn);
                    v1x += rv.x; v1y += rv.y;
                }
                *reinterpret_cast<float2*>(C + (size_t)(row+8)*ldC + cn) = make_float2(v1x, v1y);
            }
        }
    }
}

// ---------------------------------------------------------------------------
// Stage C: overlap-average + 6D -> axis-angle
// ---------------------------------------------------------------------------
__global__ void finalize_kernel(float* __restrict__ out){
    int idx = blockIdx.x*blockDim.x + threadIdx.x;
    if (idx >= LFRM*24) return;
    int t = idx/24, j = idx - 24*t;
    int lo = t - 31; if (lo < 0) lo = 0;
    int hi = t;      if (hi > NWIN-1) hi = NWIN-1;
    float s0=0,s1=0,s2=0,s3=0,s4=0,s5=0;
    for (int n = lo; n <= hi; n++){
        const float* yy = g_y + ((size_t)n*CHANS + 6*j)*WINL + (t - n);
        s0 += yy[0];      s1 += yy[WINL];   s2 += yy[2*WINL];
        s3 += yy[3*WINL]; s4 += yy[4*WINL]; s5 += yy[5*WINL];
    }
    float inv = 1.0f / (float)(hi - lo + 1);
    float a1x=s0*inv, a1y=s1*inv, a1z=s2*inv;
    float a2x=s3*inv, a2y=s4*inv, a2z=s5*inv;
    float n1 = sqrtf(a1x*a1x + a1y*a1y + a1z*a1z);
    float i1 = 1.0f / fmaxf(n1, 1e-8f);
    float b1x=a1x*i1, b1y=a1y*i1, b1z=a1z*i1;
    float d = b1x*a2x + b1y*a2y + b1z*a2z;
    float px = a2x - d*b1x, py = a2y - d*b1y, pz = a2z - d*b1z;
    float n2 = sqrtf(px*px + py*py + pz*pz);
    float i2 = 1.0f / fmaxf(n2, 1e-8f);
    float b2x=px*i2, b2y=py*i2, b2z=pz*i2;
    float b3x = b1y*b2z - b1z*b2y;
    float b3y = b1z*b2x - b1x*b2z;
    float b3z = b1x*b2y - b1y*b2x;
    float trc  = b1x + b2y + b3z;
    float cosv = (trc - 1.0f)*0.5f;
    cosv = fminf(fmaxf(cosv, -1.0f + 1e-6f), 1.0f - 1e-6f);
    float ang  = acosf(cosv);
    float sinv = sqrtf(fmaxf(1.0f - cosv*cosv, 1e-12f));
    float sc   = ang / (2.0f*sinv);
    out[t*72 + 3*j    ] = sc*(b3y - b2z);
    out[t*72 + 3*j + 1] = sc*(b1z - b3x);
    out[t*72 + 3*j + 2] = sc*(b2x - b1y);
}

// ---------------------------------------------------------------------------
extern "C" void kernel_launch(void* const* d_in, const int* in_sizes, int n_in,
                              void* d_out, int out_size){
    const float* dp    = (const float*)d_in[0];
    const float* w_in  = (const float*)d_in[1];
    const float* b_in  = (const float*)d_in[2];
    const float* w1a   = (const float*)d_in[3];
    const float* b1a   = (const float*)d_in[4];
    const float* w1b   = (const float*)d_in[5];
    const float* b1b   = (const float*)d_in[6];
    const float* w2a   = (const float*)d_in[7];
    const float* b2a   = (const float*)d_in[8];
    const float* w2b   = (const float*)d_in[9];
    const float* b2b   = (const float*)d_in[10];
    const float* w_out = (const float*)d_in[11];
    const float* b_out = (const float*)d_in[12];
    float* out = (float*)d_out;

    float *p_h, *p_r, *p_y; uint4 *p_wp;
    cudaGetSymbolAddress((void**)&p_h, g_h);
    cudaGetSymbolAddress((void**)&p_r, g_r);
    cudaGetSymbolAddress((void**)&p_y, g_y);
    cudaGetSymbolAddress((void**)&p_wp, g_wpk);

    // smem: A 2*128*36*4 + B 2*16*NT*16 bytes
    const int SM128 = 2*128*36*4 + 2*16*128*16;   // 36864 + 65536 = 102400
    const int SM32  = 2*128*36*4 + 2*16*32*16;    // 36864 + 16384 = 53248
    cudaFuncSetAttribute(gemm_tc<32, 128,512,4,2,true, true, false>, cudaFuncAttributeMaxDynamicSharedMemorySize, SM128);
    cudaFuncSetAttribute(gemm_tc<512,128,256,4,2,false,true, false>, cudaFuncAttributeMaxDynamicSharedMemorySize, SM128);
    cudaFuncSetAttribute(gemm_tc<256,128,512,4,2,false,true, true >, cudaFuncAttributeMaxDynamicSharedMemorySize, SM128);
    cudaFuncSetAttribute(gemm_tc<512,32, 32, 8,1,false,false,false>, cudaFuncAttributeMaxDynamicSharedMemorySize, SM32);

    prep_kernel<<<(WPK4 + 255)/256, 256>>>(w_in, w1a, w1b, w2a, w2b, w_out);
    aa_to_d6_kernel<<<(LFRM*24 + 255)/256, 256>>>(dp);

    // L1: h = lrelu(x @ w_in^T + b_in)     [M,32 -> 512]
    gemm_tc<32,128,512,4,2,true,true,false><<<dim3(4,MTILES), 256, SM128>>>(
        nullptr, 0, b_in, p_h, 512, nullptr, p_wp + Q1P);
    // L2: r = lrelu(h @ w1a^T + b1a)       [M,512 -> 256]
    gemm_tc<512,128,256,4,2,false,true,false><<<dim3(2,MTILES), 256, SM128>>>(
        p_h, 512, b1a, p_r, 256, nullptr, p_wp + Q2P);
    // L3: h += lrelu(r @ w1b^T + b1b)      [M,256 -> 512]
    gemm_tc<256,128,512,4,2,false,true,true><<<dim3(4,MTILES), 256, SM128>>>(
        p_r, 256, b1b, p_h, 512, p_h, p_wp + Q3P);
    // L4
    gemm_tc<512,128,256,4,2,false,true,false><<<dim3(2,MTILES), 256, SM128>>>(
        p_h, 512, b2a, p_r, 256, nullptr, p_wp + Q4P);
    // L5
    gemm_tc<256,128,512,4,2,false,true,true><<<dim3(4,MTILES), 256, SM128>>>(
        p_r, 256, b2b, p_h, 512, p_h, p_wp + Q5P);
    // L6: y = h @ w_out^T + b_out          [M,512 -> 32]
    gemm_tc<512,32,32,8,1,false,false,false><<<dim3(1,MTILES), 256, SM32>>>(
        p_h, 512, b_out, p_y, 32, nullptr, p_wp + Q6P);

    finalize_kernel<<<(LFRM*24 + 255)/256, 256>>>(out);
}

// round 15
// speedup vs baseline: 1.2532x; 1.2532x over previous
#include <cuda_runtime.h>

#define SLOPE 0.1f
#define LFRM  1024
#define CHANS 144
#define WINL  32
#define NWIN  993
#define MROWS (NWIN*CHANS)        // 142992
#define MTILES 1118
#define MPAD  (MTILES*128)        // 143104

typedef unsigned int u32;

// ---------------- device scratch (no cudaMalloc allowed) -------------------
__device__ float g_d6T[CHANS*LFRM];     // transposed: [ch][t]
__device__ float g_h[(size_t)MPAD*512];
__device__ float g_r[(size_t)MPAD*256];
__device__ float g_y[(size_t)MROWS*WINL];
// packed tf32 weight image: per layer, per K-chunk(32), per kp(16), per n:
// uint4 = (hi[k], hi[k+4], lo[k], lo[k+4]),  k = c*32 + (kp>>2)*8 + (kp&3)
#define WPK4 278528
__device__ __align__(16) uint4 g_wpk[WPK4];
#define Q1P 0
#define Q2P 8192
#define Q3P 73728
#define Q4P 139264
#define Q5P 204800
#define Q6P 270336

__device__ __forceinline__ float lrelu(float x){ return x >= 0.0f ? x : SLOPE*x; }

// ---------------- PTX helpers ----------------------------------------------
__device__ __forceinline__ u32 smem_u32(const void* p){
    u32 a; asm("{ .reg .u64 t; cvta.to.shared.u64 t, %1; cvt.u32.u64 %0, t; }" : "=r"(a) : "l"(p));
    return a;
}
__device__ __forceinline__ u32 tf32r(float x){
    u32 r; asm("cvt.rna.tf32.f32 %0, %1;" : "=r"(r) : "f"(x)); return r;
}
__device__ __forceinline__ void mma_tf32(float* d, const u32* a, u32 b0, u32 b1){
    asm volatile(
        "mma.sync.aligned.m16n8k8.row.col.f32.tf32.tf32.f32 "
        "{%0,%1,%2,%3}, {%4,%5,%6,%7}, {%8,%9}, {%0,%1,%2,%3};"
        : "+f"(d[0]), "+f"(d[1]), "+f"(d[2]), "+f"(d[3])
        : "r"(a[0]), "r"(a[1]), "r"(a[2]), "r"(a[3]), "r"(b0), "r"(b1));
}
#define CP16(dst, src) asm volatile("cp.async.cg.shared.global [%0], [%1], 16;" :: "r"(dst), "l"(src))
#define CP4(dst, src)  asm volatile("cp.async.ca.shared.global [%0], [%1], 4;"  :: "r"(dst), "l"(src))
#define CP_COMMIT()    asm volatile("cp.async.commit_group;" ::: "memory")
#define CP_WAIT(n)     asm volatile("cp.async.wait_group %0;" :: "n"(n) : "memory")

// truncation split: hi = v with low 13 mantissa bits zeroed (exact in fp32)
__device__ __forceinline__ u32 trunc_hi(float v){
    return __float_as_uint(v) & 0xFFFFE000u;
}

// ---------------------------------------------------------------------------
// Stage A: axis-angle -> 6D (transposed layout [ch][t])
// ---------------------------------------------------------------------------
__global__ void aa_to_d6_kernel(const float* __restrict__ dp){
    int idx = blockIdx.x*blockDim.x + threadIdx.x;
    if (idx >= LFRM*24) return;
    int t = idx/24, j = idx - 24*t;
    float x = dp[t*72+3*j], y = dp[t*72+3*j+1], z = dp[t*72+3*j+2];
    float ang = sqrtf(x*x + y*y + z*z);
    float inv = 1.0f / fmaxf(ang, 1e-8f);
    x *= inv; y *= inv; z *= inv;
    float s = sinf(ang), c = cosf(ang);
    float C = 1.0f - c;
    float* o = g_d6T + (size_t)(6*j)*LFRM + t;
    o[0*LFRM] = c + x*x*C;      o[1*LFRM] = x*y*C - z*s;   o[2*LFRM] = x*z*C + y*s;
    o[3*LFRM] = y*x*C + z*s;    o[4*LFRM] = c + y*y*C;     o[5*LFRM] = y*z*C - x*s;
}

// ---------------------------------------------------------------------------
// Weight prep: W[N][K] -> packed fragment image (one uint4 per thread)
// ---------------------------------------------------------------------------
__global__ void prep_kernel(const float* __restrict__ w_in, const float* __restrict__ w1a,
                            const float* __restrict__ w1b, const float* __restrict__ w2a,
                            const float* __restrict__ w2b, const float* __restrict__ w_out){
    int idx = blockIdx.x*blockDim.x + threadIdx.x;
    if (idx >= WPK4) return;
    int base, N, K; const float* W;
    if      (idx < Q2P){ base=Q1P; N=512; K=32;  W=w_in;  }
    else if (idx < Q3P){ base=Q2P; N=256; K=512; W=w1a;   }
    else if (idx < Q4P){ base=Q3P; N=512; K=256; W=w1b;   }
    else if (idx < Q5P){ base=Q4P; N=256; K=512; W=w2a;   }
    else if (idx < Q6P){ base=Q5P; N=512; K=256; W=w2b;   }
    else               { base=Q6P; N=32;  K=512; W=w_out; }
    int e = idx - base;
    int c  = e / (16*N);
    int rm = e - c*16*N;
    int kp = rm / N, n = rm - kp*N;
    int k  = c*32 + ((kp>>2)<<3) + (kp&3);
    float va = W[n*K + k], vb = W[n*K + k + 4];
    u32 ha = tf32r(va), hb = tf32r(vb);
    g_wpk[idx] = make_uint4(ha, hb,
                            tf32r(va - __uint_as_float(ha)),
                            tf32r(vb - __uint_as_float(hb)));
}

// ---------------------------------------------------------------------------
// GEMM: C[128 x NT per CTA] = act(A @ W^T + b) [+res], 3xTF32 on mma.sync.
// grid = (n-tiles, m-tiles): col-tile fast axis -> sibling CTAs share A in L2.
// 256 threads (MW x NW warp grid), 2 CTAs/SM. cp.async double-buffered K=32.
// A: fp32 smem (ASTR 36), trunc-hi split, raw-bits lo.
// B: packed uint4, BSTR = NT+4 (load-bearing padding: staggers tig banks).
// ---------------------------------------------------------------------------
template<int KTOT, int NT, int NFULL, int MW, int NW, bool GATHER, bool RELU, bool RES>
__global__ void __launch_bounds__(256, 2)
gemm_tc(const float* __restrict__ A, int ldA,
        const float* __restrict__ bias,
        float* __restrict__ C, int ldC,
        const float* __restrict__ res,
        const uint4* __restrict__ Wp)
{
    constexpr int KC = 32, NCH = KTOT/32;
    constexpr int WM = 128/MW, WN = NT/NW, MF = WM/16, NF = WN/8;
    constexpr int ASTR = 36, BSTR4 = NT + 4;
    constexpr int AELE = 128*ASTR, BELE4 = 16*BSTR4;

    extern __shared__ float sm[];
    float* Ab[2] = { sm, sm + AELE };
    uint4* Bq[2];
    Bq[0] = (uint4*)(sm + 2*AELE);
    Bq[1] = Bq[0] + BELE4;

    const int tid = threadIdx.x, lane = tid & 31, wid = tid >> 5;
    const int gid = lane >> 2, tig = lane & 3;
    const int warp_n = wid % NW, warp_m = wid / NW;
    const int m0 = blockIdx.y * 128;
    const int col0 = blockIdx.x * NT;

    float acc[MF][NF][4];
    #pragma unroll
    for (int i = 0; i < MF; i++)
        #pragma unroll
        for (int j = 0; j < NF; j++)
            #pragma unroll
            for (int q = 0; q < 4; q++) acc[i][j][q] = 0.0f;

    auto stage = [&](int c, int b){
        if (GATHER){
            // transposed d6: k contiguous -> coalesced CP4
            for (int idx = tid; idx < 128*KC; idx += 256){
                int r = idx >> 5, k = idx & 31;
                int m = m0 + r; if (m >= MROWS) m = MROWS - 1;
                int n = m / CHANS, ch = m - n*CHANS;
                CP4(smem_u32(&Ab[b][r*ASTR + k]),
                    g_d6T + (size_t)ch*LFRM + n + c*KC + k);
            }
        } else {
            for (int idx = tid; idx < 128*8; idx += 256){
                int r = idx >> 3, q = idx & 7;
                CP16(smem_u32(&Ab[b][r*ASTR + 4*q]),
                     A + (size_t)(m0 + r)*ldA + c*KC + 4*q);
            }
        }
        for (int idx = tid; idx < 16*NT; idx += 256){
            int kp = idx / NT, n = idx % NT;
            CP16(smem_u32(&Bq[b][kp*BSTR4 + n]),
                 Wp + (size_t)(c*16 + kp)*NFULL + col0 + n);
        }
    };

    stage(0, 0); CP_COMMIT();
    if (NCH > 1){ stage(1, 1); CP_COMMIT(); }

    for (int c = 0; c < NCH; c++){
        if (c == NCH-1) { CP_WAIT(0); } else { CP_WAIT(1); }
        __syncthreads();
        int b = c & 1;
        const float* As = Ab[b];
        const uint4* Bs = Bq[b];
        #pragma unroll
        for (int ks = 0; ks < KC/8; ks++){
            int kk = ks*8 + tig;
            int kpr = ks*4 + tig;
            // ---- A fragments: trunc hi (LOP3), raw-bits lo (FADD only) ----
            u32 ah[MF][4], al[MF][4];
            #pragma unroll
            for (int mf = 0; mf < MF; mf++){
                int r0 = warp_m*WM + mf*16 + gid;
                float x0 = As[r0*ASTR + kk];
                float x1 = As[(r0+8)*ASTR + kk];
                float x2 = As[r0*ASTR + kk + 4];
                float x3 = As[(r0+8)*ASTR + kk + 4];
                ah[mf][0] = trunc_hi(x0); al[mf][0] = __float_as_uint(x0 - __uint_as_float(ah[mf][0]));
                ah[mf][1] = trunc_hi(x1); al[mf][1] = __float_as_uint(x1 - __uint_as_float(ah[mf][1]));
                ah[mf][2] = trunc_hi(x2); al[mf][2] = __float_as_uint(x2 - __uint_as_float(ah[mf][2]));
                ah[mf][3] = trunc_hi(x3); al[mf][3] = __float_as_uint(x3 - __uint_as_float(ah[mf][3]));
            }
            // ---- B fragments: one LDS.128 per nf ----
            uint4 bq[NF];
            #pragma unroll
            for (int nf = 0; nf < NF; nf++)
                bq[nf] = Bs[kpr*BSTR4 + warp_n*WN + nf*8 + gid];
            // ---- 3 term sweeps ----
            #pragma unroll
            for (int nf = 0; nf < NF; nf++)
                #pragma unroll
                for (int mf = 0; mf < MF; mf++)
                    mma_tf32(acc[mf][nf], ah[mf], bq[nf].x, bq[nf].y);
            #pragma unroll
            for (int nf = 0; nf < NF; nf++)
                #pragma unroll
                for (int mf = 0; mf < MF; mf++)
                    mma_tf32(acc[mf][nf], ah[mf], bq[nf].z, bq[nf].w);
            #pragma unroll
            for (int nf = 0; nf < NF; nf++)
                #pragma unroll
                for (int mf = 0; mf < MF; mf++)
                    mma_tf32(acc[mf][nf], al[mf], bq[nf].x, bq[nf].y);
        }
        if (c + 2 < NCH){
            __syncthreads();
            stage(c + 2, b); CP_COMMIT();
        }
    }

    // ---- epilogue ----
    #pragma unroll
    for (int mf = 0; mf < MF; mf++){
        int row = m0 + warp_m*WM + mf*16 + gid;
        #pragma unroll
        for (int nf = 0; nf < NF; nf++){
            int cn = col0 + warp_n*WN + nf*8 + 2*tig;
            float2 bv = *reinterpret_cast<const float2*>(bias + cn);
            float v0x = acc[mf][nf][0] + bv.x, v0y = acc[mf][nf][1] + bv.y;
            float v1x = acc[mf][nf][2] + bv.x, v1y = acc[mf][nf][3] + bv.y;
            if (RELU){ v0x = lrelu(v0x); v0y = lrelu(v0y); v1x = lrelu(v1x); v1y = lrelu(v1y); }
            if (row < MROWS){
                if (RES){
                    float2 rv = *reinterpret_cast<const float2*>(res + (size_t)row*ldC + cn);
                    v0x += rv.x; v0y += rv.y;
                }
                *reinterpret_cast<float2*>(C + (size_t)row*ldC + cn) = make_float2(v0x, v0y);
            }
            if (row + 8 < MROWS){
                if (RES){
                    float2 rv = *reinterpret_cast<const float2*>(res + (size_t)(row+8)*ldC + cn);
                    v1x += rv.x; v1y += rv.y;
                }
                *reinterpret_cast<float2*>(C + (size_t)(row+8)*ldC + cn) = make_float2(v1x, v1y);
            }
        }
    }
}

// ---------------------------------------------------------------------------
// Stage C: overlap-average + 6D -> axis-angle
// ---------------------------------------------------------------------------
__global__ void finalize_kernel(float* __restrict__ out){
    int idx = blockIdx.x*blockDim.x + threadIdx.x;
    if (idx >= LFRM*24) return;
    int t = idx/24, j = idx - 24*t;
    int lo = t - 31; if (lo < 0) lo = 0;
    int hi = t;      if (hi > NWIN-1) hi = NWIN-1;
    float s0=0,s1=0,s2=0,s3=0,s4=0,s5=0;
    for (int n = lo; n <= hi; n++){
        const float* yy = g_y + ((size_t)n*CHANS + 6*j)*WINL + (t - n);
        s0 += yy[0];      s1 += yy[WINL];   s2 += yy[2*WINL];
        s3 += yy[3*WINL]; s4 += yy[4*WINL]; s5 += yy[5*WINL];
    }
    float inv = 1.0f / (float)(hi - lo + 1);
    float a1x=s0*inv, a1y=s1*inv, a1z=s2*inv;
    float a2x=s3*inv, a2y=s4*inv, a2z=s5*inv;
    float n1 = sqrtf(a1x*a1x + a1y*a1y + a1z*a1z);
    float i1 = 1.0f / fmaxf(n1, 1e-8f);
    float b1x=a1x*i1, b1y=a1y*i1, b1z=a1z*i1;
    float d = b1x*a2x + b1y*a2y + b1z*a2z;
    float px = a2x - d*b1x, py = a2y - d*b1y, pz = a2z - d*b1z;
    float n2 = sqrtf(px*px + py*py + pz*pz);
    float i2 = 1.0f / fmaxf(n2, 1e-8f);
    float b2x=px*i2, b2y=py*i2, b2z=pz*i2;
    float b3x = b1y*b2z - b1z*b2y;
    float b3y = b1z*b2x - b1x*b2z;
    float b3z = b1x*b2y - b1y*b2x;
    float trc  = b1x + b2y + b3z;
    float cosv = (trc - 1.0f)*0.5f;
    cosv = fminf(fmaxf(cosv, -1.0f + 1e-6f), 1.0f - 1e-6f);
    float ang  = acosf(cosv);
    float sinv = sqrtf(fmaxf(1.0f - cosv*cosv, 1e-12f));
    float sc   = ang / (2.0f*sinv);
    out[t*72 + 3*j    ] = sc*(b3y - b2z);
    out[t*72 + 3*j + 1] = sc*(b1z - b3x);
    out[t*72 + 3*j + 2] = sc*(b2x - b1y);
}

// ---------------------------------------------------------------------------
extern "C" void kernel_launch(void* const* d_in, const int* in_sizes, int n_in,
                              void* d_out, int out_size){
    const float* dp    = (const float*)d_in[0];
    const float* w_in  = (const float*)d_in[1];
    const float* b_in  = (const float*)d_in[2];
    const float* w1a   = (const float*)d_in[3];
    const float* b1a   = (const float*)d_in[4];
    const float* w1b   = (const float*)d_in[5];
    const float* b1b   = (const float*)d_in[6];
    const float* w2a   = (const float*)d_in[7];
    const float* b2a   = (const float*)d_in[8];
    const float* w2b   = (const float*)d_in[9];
    const float* b2b   = (const float*)d_in[10];
    const float* w_out = (const float*)d_in[11];
    const float* b_out = (const float*)d_in[12];
    float* out = (float*)d_out;

    float *p_h, *p_r, *p_y; uint4 *p_wp;
    cudaGetSymbolAddress((void**)&p_h, g_h);
    cudaGetSymbolAddress((void**)&p_r, g_r);
    cudaGetSymbolAddress((void**)&p_y, g_y);
    cudaGetSymbolAddress((void**)&p_wp, g_wpk);

    // smem: A 2*128*36*4 + B 2*16*(NT+4)*16 bytes
    const int SM128 = 2*128*36*4 + 2*16*132*16;   // 36864 + 67584 = 104448
    const int SM32  = 2*128*36*4 + 2*16*36*16;    // 36864 + 18432 = 55296
    cudaFuncSetAttribute(gemm_tc<32, 128,512,4,2,true, true, false>, cudaFuncAttributeMaxDynamicSharedMemorySize, SM128);
    cudaFuncSetAttribute(gemm_tc<512,128,256,4,2,false,true, false>, cudaFuncAttributeMaxDynamicSharedMemorySize, SM128);
    cudaFuncSetAttribute(gemm_tc<256,128,512,4,2,false,true, true >, cudaFuncAttributeMaxDynamicSharedMemorySize, SM128);
    cudaFuncSetAttribute(gemm_tc<512,32, 32, 8,1,false,false,false>, cudaFuncAttributeMaxDynamicSharedMemorySize, SM32);

    prep_kernel<<<(WPK4 + 255)/256, 256>>>(w_in, w1a, w1b, w2a, w2b, w_out);
    aa_to_d6_kernel<<<(LFRM*24 + 255)/256, 256>>>(dp);

    // L1: h = lrelu(x @ w_in^T + b_in)     [M,32 -> 512]
    gemm_tc<32,128,512,4,2,true,true,false><<<dim3(4,MTILES), 256, SM128>>>(
        nullptr, 0, b_in, p_h, 512, nullptr, p_wp + Q1P);
    // L2: r = lrelu(h @ w1a^T + b1a)       [M,512 -> 256]
    gemm_tc<512,128,256,4,2,false,true,false><<<dim3(2,MTILES), 256, SM128>>>(
        p_h, 512, b1a, p_r, 256, nullptr, p_wp + Q2P);
    // L3: h += lrelu(r @ w1b^T + b1b)      [M,256 -> 512]
    gemm_tc<256,128,512,4,2,false,true,true><<<dim3(4,MTILES), 256, SM128>>>(
        p_r, 256, b1b, p_h, 512, p_h, p_wp + Q3P);
    // L4
    gemm_tc<512,128,256,4,2,false,true,false><<<dim3(2,MTILES), 256, SM128>>>(
        p_h, 512, b2a, p_r, 256, nullptr, p_wp + Q4P);
    // L5
    gemm_tc<256,128,512,4,2,false,true,true><<<dim3(4,MTILES), 256, SM128>>>(
        p_r, 256, b2b, p_h, 512, p_h, p_wp + Q5P);
    // L6: y = h @ w_out^T + b_out          [M,512 -> 32]
    gemm_tc<512,32,32,8,1,false,false,false><<<dim3(1,MTILES), 256, SM32>>>(
        p_h, 512, b_out, p_y, 32, nullptr, p_wp + Q6P);

    finalize_kernel<<<(LFRM*24 + 255)/256, 256>>>(out);
}

// round 16
// speedup vs baseline: 1.2598x; 1.0053x over previous
#include <cuda_runtime.h>

#define SLOPE 0.1f
#define LFRM  1024
#define CHANS 144
#define WINL  32
#define NWIN  993
#define MROWS (NWIN*CHANS)        // 142992
#define MTILES 1118
#define MPAD  (MTILES*128)        // 143104

typedef unsigned int u32;

// ---------------- device scratch (no cudaMalloc allowed) -------------------
__device__ float g_d6T[CHANS*LFRM];     // transposed: [ch][t]
__device__ float g_h[(size_t)MPAD*512];
__device__ float g_r[(size_t)MPAD*256];
__device__ float g_yT[(size_t)WINL*MROWS];   // transposed: [w][m]
// packed tf32 weight image: per layer, per K-chunk(32), per kp(16), per n:
// uint4 = (hi[k], hi[k+4], lo[k], lo[k+4]),  k = c*32 + (kp>>2)*8 + (kp&3)
#define WPK4 278528
__device__ __align__(16) uint4 g_wpk[WPK4];
#define Q1P 0
#define Q2P 8192
#define Q3P 73728
#define Q4P 139264
#define Q5P 204800
#define Q6P 270336

__device__ __forceinline__ float lrelu(float x){ return x >= 0.0f ? x : SLOPE*x; }

// ---------------- PTX helpers ----------------------------------------------
__device__ __forceinline__ u32 smem_u32(const void* p){
    u32 a; asm("{ .reg .u64 t; cvta.to.shared.u64 t, %1; cvt.u32.u64 %0, t; }" : "=r"(a) : "l"(p));
    return a;
}
__device__ __forceinline__ u32 tf32r(float x){
    u32 r; asm("cvt.rna.tf32.f32 %0, %1;" : "=r"(r) : "f"(x)); return r;
}
__device__ __forceinline__ void mma_tf32(float* d, const u32* a, u32 b0, u32 b1){
    asm volatile(
        "mma.sync.aligned.m16n8k8.row.col.f32.tf32.tf32.f32 "
        "{%0,%1,%2,%3}, {%4,%5,%6,%7}, {%8,%9}, {%0,%1,%2,%3};"
        : "+f"(d[0]), "+f"(d[1]), "+f"(d[2]), "+f"(d[3])
        : "r"(a[0]), "r"(a[1]), "r"(a[2]), "r"(a[3]), "r"(b0), "r"(b1));
}
#define CP16(dst, src) asm volatile("cp.async.cg.shared.global [%0], [%1], 16;" :: "r"(dst), "l"(src))
#define CP4(dst, src)  asm volatile("cp.async.ca.shared.global [%0], [%1], 4;"  :: "r"(dst), "l"(src))
#define CP_COMMIT()    asm volatile("cp.async.commit_group;" ::: "memory")
#define CP_WAIT(n)     asm volatile("cp.async.wait_group %0;" :: "n"(n) : "memory")

// truncation split: hi = v with low 13 mantissa bits zeroed (exact in fp32)
__device__ __forceinline__ u32 trunc_hi(float v){
    return __float_as_uint(v) & 0xFFFFE000u;
}

// ---------------------------------------------------------------------------
// Init kernel: weight prep (blocks [0, PREPB)) + aa->6D (blocks [PREPB, ..))
// ---------------------------------------------------------------------------
#define PREPB ((WPK4 + 255)/256)
#define AAB   ((LFRM*24 + 255)/256)
__global__ void init_kernel(const float* __restrict__ dp,
                            const float* __restrict__ w_in, const float* __restrict__ w1a,
                            const float* __restrict__ w1b, const float* __restrict__ w2a,
                            const float* __restrict__ w2b, const float* __restrict__ w_out){
    if (blockIdx.x < PREPB){
        int idx = blockIdx.x*blockDim.x + threadIdx.x;
        if (idx >= WPK4) return;
        int base, N, K; const float* W;
        if      (idx < Q2P){ base=Q1P; N=512; K=32;  W=w_in;  }
        else if (idx < Q3P){ base=Q2P; N=256; K=512; W=w1a;   }
        else if (idx < Q4P){ base=Q3P; N=512; K=256; W=w1b;   }
        else if (idx < Q5P){ base=Q4P; N=256; K=512; W=w2a;   }
        else if (idx < Q6P){ base=Q5P; N=512; K=256; W=w2b;   }
        else               { base=Q6P; N=32;  K=512; W=w_out; }
        int e = idx - base;
        int c  = e / (16*N);
        int rm = e - c*16*N;
        int kp = rm / N, n = rm - kp*N;
        int k  = c*32 + ((kp>>2)<<3) + (kp&3);
        float va = W[n*K + k], vb = W[n*K + k + 4];
        u32 ha = tf32r(va), hb = tf32r(vb);
        g_wpk[idx] = make_uint4(ha, hb,
                                tf32r(va - __uint_as_float(ha)),
                                tf32r(vb - __uint_as_float(hb)));
    } else {
        int idx = (blockIdx.x - PREPB)*blockDim.x + threadIdx.x;
        if (idx >= LFRM*24) return;
        int t = idx/24, j = idx - 24*t;
        float x = dp[t*72+3*j], y = dp[t*72+3*j+1], z = dp[t*72+3*j+2];
        float ang = sqrtf(x*x + y*y + z*z);
        float inv = 1.0f / fmaxf(ang, 1e-8f);
        x *= inv; y *= inv; z *= inv;
        float s = sinf(ang), c = cosf(ang);
        float C = 1.0f - c;
        float* o = g_d6T + (size_t)(6*j)*LFRM + t;
        o[0*LFRM] = c + x*x*C;      o[1*LFRM] = x*y*C - z*s;   o[2*LFRM] = x*z*C + y*s;
        o[3*LFRM] = y*x*C + z*s;    o[4*LFRM] = c + y*y*C;     o[5*LFRM] = y*z*C - x*s;
    }
}

// ---------------------------------------------------------------------------
// GEMM: C[128 x NT per CTA] = act(A @ W^T + b) [+res], 3xTF32 on mma.sync.
// grid = (n-tiles, m-tiles): col-tile fast axis -> sibling CTAs share A in L2.
// 256 threads (MW x NW warp grid), 2 CTAs/SM. cp.async double-buffered K=32.
// A: fp32 smem (ASTR 36), trunc-hi split, raw-bits lo.
// B: packed uint4, BSTR = NT+4 (load-bearing padding: staggers tig banks).
// FPOUT: writes transposed y [w][m].
// ---------------------------------------------------------------------------
template<int KTOT, int NT, int NFULL, int MW, int NW, bool GATHER, bool RELU, bool RES, bool FPOUT>
__global__ void __launch_bounds__(256, 2)
gemm_tc(const float* __restrict__ A, int ldA,
        const float* __restrict__ bias,
        float* __restrict__ C, int ldC,
        const float* __restrict__ res,
        const uint4* __restrict__ Wp)
{
    constexpr int KC = 32, NCH = KTOT/32;
    constexpr int WM = 128/MW, WN = NT/NW, MF = WM/16, NF = WN/8;
    constexpr int ASTR = 36, BSTR4 = NT + 4;
    constexpr int AELE = 128*ASTR, BELE4 = 16*BSTR4;

    extern __shared__ float sm[];
    float* Ab[2] = { sm, sm + AELE };
    uint4* Bq[2];
    Bq[0] = (uint4*)(sm + 2*AELE);
    Bq[1] = Bq[0] + BELE4;

    const int tid = threadIdx.x, lane = tid & 31, wid = tid >> 5;
    const int gid = lane >> 2, tig = lane & 3;
    const int warp_n = wid % NW, warp_m = wid / NW;
    const int m0 = blockIdx.y * 128;
    const int col0 = blockIdx.x * NT;

    float acc[MF][NF][4];
    #pragma unroll
    for (int i = 0; i < MF; i++)
        #pragma unroll
        for (int j = 0; j < NF; j++)
            #pragma unroll
            for (int q = 0; q < 4; q++) acc[i][j][q] = 0.0f;

    auto stage = [&](int c, int b){
        if (GATHER){
            // transposed d6: k contiguous -> coalesced CP4
            for (int idx = tid; idx < 128*KC; idx += 256){
                int r = idx >> 5, k = idx & 31;
                int m = m0 + r; if (m >= MROWS) m = MROWS - 1;
                int n = m / CHANS, ch = m - n*CHANS;
                CP4(smem_u32(&Ab[b][r*ASTR + k]),
                    g_d6T + (size_t)ch*LFRM + n + c*KC + k);
            }
        } else {
            for (int idx = tid; idx < 128*8; idx += 256){
                int r = idx >> 3, q = idx & 7;
                CP16(smem_u32(&Ab[b][r*ASTR + 4*q]),
                     A + (size_t)(m0 + r)*ldA + c*KC + 4*q);
            }
        }
        for (int idx = tid; idx < 16*NT; idx += 256){
            int kp = idx / NT, n = idx % NT;
            CP16(smem_u32(&Bq[b][kp*BSTR4 + n]),
                 Wp + (size_t)(c*16 + kp)*NFULL + col0 + n);
        }
    };

    stage(0, 0); CP_COMMIT();
    if (NCH > 1){ stage(1, 1); CP_COMMIT(); }

    for (int c = 0; c < NCH; c++){
        if (c == NCH-1) { CP_WAIT(0); } else { CP_WAIT(1); }
        __syncthreads();
        int b = c & 1;
        const float* As = Ab[b];
        const uint4* Bs = Bq[b];
        #pragma unroll
        for (int ks = 0; ks < KC/8; ks++){
            int kk = ks*8 + tig;
            int kpr = ks*4 + tig;
            // ---- A fragments: trunc hi (LOP3), raw-bits lo (FADD only) ----
            u32 ah[MF][4], al[MF][4];
            #pragma unroll
            for (int mf = 0; mf < MF; mf++){
                int r0 = warp_m*WM + mf*16 + gid;
                float x0 = As[r0*ASTR + kk];
                float x1 = As[(r0+8)*ASTR + kk];
                float x2 = As[r0*ASTR + kk + 4];
                float x3 = As[(r0+8)*ASTR + kk + 4];
                ah[mf][0] = trunc_hi(x0); al[mf][0] = __float_as_uint(x0 - __uint_as_float(ah[mf][0]));
                ah[mf][1] = trunc_hi(x1); al[mf][1] = __float_as_uint(x1 - __uint_as_float(ah[mf][1]));
                ah[mf][2] = trunc_hi(x2); al[mf][2] = __float_as_uint(x2 - __uint_as_float(ah[mf][2]));
                ah[mf][3] = trunc_hi(x3); al[mf][3] = __float_as_uint(x3 - __uint_as_float(ah[mf][3]));
            }
            // ---- B fragments: one LDS.128 per nf ----
            uint4 bq[NF];
            #pragma unroll
            for (int nf = 0; nf < NF; nf++)
                bq[nf] = Bs[kpr*BSTR4 + warp_n*WN + nf*8 + gid];
            // ---- 3 term sweeps ----
            #pragma unroll
            for (int nf = 0; nf < NF; nf++)
                #pragma unroll
                for (int mf = 0; mf < MF; mf++)
                    mma_tf32(acc[mf][nf], ah[mf], bq[nf].x, bq[nf].y);
            #pragma unroll
            for (int nf = 0; nf < NF; nf++)
                #pragma unroll
                for (int mf = 0; mf < MF; mf++)
                    mma_tf32(acc[mf][nf], ah[mf], bq[nf].z, bq[nf].w);
            #pragma unroll
            for (int nf = 0; nf < NF; nf++)
                #pragma unroll
                for (int mf = 0; mf < MF; mf++)
                    mma_tf32(acc[mf][nf], al[mf], bq[nf].x, bq[nf].y);
        }
        if (c + 2 < NCH){
            __syncthreads();
            stage(c + 2, b); CP_COMMIT();
        }
    }

    // ---- epilogue ----
    #pragma unroll
    for (int mf = 0; mf < MF; mf++){
        int row = m0 + warp_m*WM + mf*16 + gid;
        #pragma unroll
        for (int nf = 0; nf < NF; nf++){
            int cn = col0 + warp_n*WN + nf*8 + 2*tig;
            float2 bv = *reinterpret_cast<const float2*>(bias + cn);
            float v0x = acc[mf][nf][0] + bv.x, v0y = acc[mf][nf][1] + bv.y;
            float v1x = acc[mf][nf][2] + bv.x, v1y = acc[mf][nf][3] + bv.y;
            if (RELU){ v0x = lrelu(v0x); v0y = lrelu(v0y); v1x = lrelu(v1x); v1y = lrelu(v1y); }
            if (FPOUT){
                // transposed y [w][m]: col-major per output column
                if (row < MROWS){
                    C[(size_t)cn*MROWS + row]     = v0x;
                    C[(size_t)(cn+1)*MROWS + row] = v0y;
                }
                if (row + 8 < MROWS){
                    C[(size_t)cn*MROWS + row + 8]     = v1x;
                    C[(size_t)(cn+1)*MROWS + row + 8] = v1y;
                }
            } else {
                if (row < MROWS){
                    if (RES){
                        float2 rv = *reinterpret_cast<const float2*>(res + (size_t)row*ldC + cn);
                        v0x += rv.x; v0y += rv.y;
                    }
                    *reinterpret_cast<float2*>(C + (size_t)row*ldC + cn) = make_float2(v0x, v0y);
                }
                if (row + 8 < MROWS){
                    if (RES){
                        float2 rv = *reinterpret_cast<const float2*>(res + (size_t)(row+8)*ldC + cn);
                        v1x += rv.x; v1y += rv.y;
                    }
                    *reinterpret_cast<float2*>(C + (size_t)(row+8)*ldC + cn) = make_float2(v1x, v1y);
                }
            }
        }
    }
}

// ---------------------------------------------------------------------------
// Stage C: overlap-average + 6D -> axis-angle (reads transposed y [w][m])
// ---------------------------------------------------------------------------
__global__ void finalize_kernel(float* __restrict__ out){
    int idx = blockIdx.x*blockDim.x + threadIdx.x;
    if (idx >= LFRM*24) return;
    int t = idx/24, j = idx - 24*t;
    int lo = t - 31; if (lo < 0) lo = 0;
    int hi = t;      if (hi > NWIN-1) hi = NWIN-1;
    float s0=0,s1=0,s2=0,s3=0,s4=0,s5=0;
    for (int n = lo; n <= hi; n++){
        size_t base = (size_t)(t - n)*MROWS + (size_t)n*CHANS + 6*j;
        s0 += g_yT[base];     s1 += g_yT[base+1];  s2 += g_yT[base+2];
        s3 += g_yT[base+3];   s4 += g_yT[base+4];  s5 += g_yT[base+5];
    }
    float inv = 1.0f / (float)(hi - lo + 1);
    float a1x=s0*inv, a1y=s1*inv, a1z=s2*inv;
    float a2x=s3*inv, a2y=s4*inv, a2z=s5*inv;
    float n1 = sqrtf(a1x*a1x + a1y*a1y + a1z*a1z);
    float i1 = 1.0f / fmaxf(n1, 1e-8f);
    float b1x=a1x*i1, b1y=a1y*i1, b1z=a1z*i1;
    float d = b1x*a2x + b1y*a2y + b1z*a2z;
    float px = a2x - d*b1x, py = a2y - d*b1y, pz = a2z - d*b1z;
    float n2 = sqrtf(px*px + py*py + pz*pz);
    float i2 = 1.0f / fmaxf(n2, 1e-8f);
    float b2x=px*i2, b2y=py*i2, b2z=pz*i2;
    float b3x = b1y*b2z - b1z*b2y;
    float b3y = b1z*b2x - b1x*b2z;
    float b3z = b1x*b2y - b1y*b2x;
    float trc  = b1x + b2y + b3z;
    float cosv = (trc - 1.0f)*0.5f;
    cosv = fminf(fmaxf(cosv, -1.0f + 1e-6f), 1.0f - 1e-6f);
    float ang  = acosf(cosv);
    float sinv = sqrtf(fmaxf(1.0f - cosv*cosv, 1e-12f));
    float sc   = ang / (2.0f*sinv);
    out[t*72 + 3*j    ] = sc*(b3y - b2z);
    out[t*72 + 3*j + 1] = sc*(b1z - b3x);
    out[t*72 + 3*j + 2] = sc*(b2x - b1y);
}

// ---------------------------------------------------------------------------
extern "C" void kernel_launch(void* const* d_in, const int* in_sizes, int n_in,
                              void* d_out, int out_size){
    const float* dp    = (const float*)d_in[0];
    const float* w_in  = (const float*)d_in[1];
    const float* b_in  = (const float*)d_in[2];
    const float* w1a   = (const float*)d_in[3];
    const float* b1a   = (const float*)d_in[4];
    const float* w1b   = (const float*)d_in[5];
    const float* b1b   = (const float*)d_in[6];
    const float* w2a   = (const float*)d_in[7];
    const float* b2a   = (const float*)d_in[8];
    const float* w2b   = (const float*)d_in[9];
    const float* b2b   = (const float*)d_in[10];
    const float* w_out = (const float*)d_in[11];
    const float* b_out = (const float*)d_in[12];
    float* out = (float*)d_out;

    float *p_h, *p_r, *p_y; uint4 *p_wp;
    cudaGetSymbolAddress((void**)&p_h, g_h);
    cudaGetSymbolAddress((void**)&p_r, g_r);
    cudaGetSymbolAddress((void**)&p_y, g_yT);
    cudaGetSymbolAddress((void**)&p_wp, g_wpk);

    // smem: A 2*128*36*4 + B 2*16*(NT+4)*16 bytes
    const int SM128 = 2*128*36*4 + 2*16*132*16;   // 36864 + 67584 = 104448
    const int SM32  = 2*128*36*4 + 2*16*36*16;    // 36864 + 18432 = 55296
    cudaFuncSetAttribute(gemm_tc<32, 128,512,4,2,true, true, false,false>, cudaFuncAttributeMaxDynamicSharedMemorySize, SM128);
    cudaFuncSetAttribute(gemm_tc<512,128,256,4,2,false,true, false,false>, cudaFuncAttributeMaxDynamicSharedMemorySize, SM128);
    cudaFuncSetAttribute(gemm_tc<256,128,512,4,2,false,true, true, false>, cudaFuncAttributeMaxDynamicSharedMemorySize, SM128);
    cudaFuncSetAttribute(gemm_tc<512,32, 32, 8,1,false,false,false,true >, cudaFuncAttributeMaxDynamicSharedMemorySize, SM32);

    init_kernel<<<PREPB + AAB, 256>>>(dp, w_in, w1a, w1b, w2a, w2b, w_out);

    // L1: h = lrelu(x @ w_in^T + b_in)     [M,32 -> 512]
    gemm_tc<32,128,512,4,2,true,true,false,false><<<dim3(4,MTILES), 256, SM128>>>(
        nullptr, 0, b_in, p_h, 512, nullptr, p_wp + Q1P);
    // L2: r = lrelu(h @ w1a^T + b1a)       [M,512 -> 256]
    gemm_tc<512,128,256,4,2,false,true,false,false><<<dim3(2,MTILES), 256, SM128>>>(
        p_h, 512, b1a, p_r, 256, nullptr, p_wp + Q2P);
    // L3: h += lrelu(r @ w1b^T + b1b)      [M,256 -> 512]
    gemm_tc<256,128,512,4,2,false,true,true,false><<<dim3(4,MTILES), 256, SM128>>>(
        p_r, 256, b1b, p_h, 512, p_h, p_wp + Q3P);
    // L4
    gemm_tc<512,128,256,4,2,false,true,false,false><<<dim3(2,MTILES), 256, SM128>>>(
        p_h, 512, b2a, p_r, 256, nullptr, p_wp + Q4P);
    // L5
    gemm_tc<256,128,512,4,2,false,true,true,false><<<dim3(4,MTILES), 256, SM128>>>(
        p_r, 256, b2b, p_h, 512, p_h, p_wp + Q5P);
    // L6: y = h @ w_out^T + b_out          [M,512 -> 32], transposed out
    gemm_tc<512,32,32,8,1,false,false,false,true><<<dim3(1,MTILES), 256, SM32>>>(
        p_h, 512, b_out, p_y, 32, nullptr, p_wp + Q6P);

    finalize_kernel<<<AAB, 256>>>(out);
}